// round 16
// baseline (speedup 1.0000x reference)
#include <cuda_runtime.h>
#include <cuda_fp16.h>
#include <cstdint>

#define N_ 16
#define C_ 256
#define T_ 300
#define V_ 25
#define K_ 3
#define TK_ 9
#define J_ 7500
#define KD1 768            // GEMM1 K-dim (k,ci)
#define BN_EPS 1e-5f

// static device scratch
__device__ __align__(256) __half xa_buf[(size_t)N_ * J_ * KD1];   // 184 MB
__device__ __align__(256) __half gt_buf[(size_t)N_ * J_ * C_];    // 61.4 MB
__device__ __align__(256) __half wt2_buf[TK_ * C_ * C_];          // [dt][co][ci]
__device__ __align__(256) __half wa_buf[C_ * KD1];                // [co][(k,ci)]
__device__ __align__(256) __half amh_buf[80 * 32];                // [kw-row][v] fp16
__device__ float bcw_buf[C_ * V_];                                // bias*sum(AM)

// ---------------------------------------------------------------------------
// PTX helpers
// ---------------------------------------------------------------------------
__device__ __forceinline__ uint32_t smem_u32(const void* p) {
    uint32_t a;
    asm("{ .reg .u64 t; cvta.to.shared.u64 t, %1; cvt.u32.u64 %0, t; }" : "=r"(a) : "l"(p));
    return a;
}
__device__ __forceinline__ void ldsm4(uint32_t* r, uint32_t addr) {
    asm volatile("ldmatrix.sync.aligned.m8n8.x4.shared.b16 {%0,%1,%2,%3}, [%4];"
                 : "=r"(r[0]), "=r"(r[1]), "=r"(r[2]), "=r"(r[3]) : "r"(addr));
}
__device__ __forceinline__ void mma16816(float* c, const uint32_t* a,
                                         uint32_t b0, uint32_t b1) {
    asm("mma.sync.aligned.m16n8k16.row.col.f32.f16.f16.f32 "
        "{%0,%1,%2,%3}, {%4,%5,%6,%7}, {%8,%9}, {%0,%1,%2,%3};"
        : "+f"(c[0]), "+f"(c[1]), "+f"(c[2]), "+f"(c[3])
        : "r"(a[0]), "r"(a[1]), "r"(a[2]), "r"(a[3]), "r"(b0), "r"(b1));
}
__device__ __forceinline__ void cpa16(uint32_t dst, const void* src, int srcsize) {
    asm volatile("cp.async.cg.shared.global [%0], [%1], 16, %2;"
                 :: "r"(dst), "l"(src), "r"(srcsize));
}
__device__ __forceinline__ void cpa_commit() {
    asm volatile("cp.async.commit_group;" ::: "memory");
}
template <int NN>
__device__ __forceinline__ void cpa_wait() {
    asm volatile("cp.async.wait_group %0;" :: "n"(NN) : "memory");
}

// ---------------------------------------------------------------------------
// merged prep kernel: wt2 | wa | amh | bcw by blockIdx range  (proven)
// ---------------------------------------------------------------------------
#define PREP_WT2_BLKS 2304
#define PREP_WA_BLKS  768
#define PREP_AMH_BLKS 10
#define PREP_BLKS (PREP_WT2_BLKS + PREP_WA_BLKS + PREP_AMH_BLKS + 1)

__global__ void prep_kernel(const float* __restrict__ tw, const float* __restrict__ cw,
                            const float* __restrict__ A, const float* __restrict__ Mm,
                            const float* __restrict__ bias) {
    const int b = blockIdx.x;
    const int tid = threadIdx.x;
    if (b < PREP_WT2_BLKS) {
        int i = b * 256 + tid;
        if (i < TK_ * C_ * C_) {
            int dt = i / (C_ * C_);
            int r  = i - dt * C_ * C_;
            int co = r >> 8;
            int ci = r & 255;
            wt2_buf[i] = __float2half_rn(tw[(co * C_ + ci) * TK_ + dt]);
        }
    } else if (b < PREP_WT2_BLKS + PREP_WA_BLKS) {
        int i = (b - PREP_WT2_BLKS) * 256 + tid;
        if (i < C_ * KD1) {
            int co = i / KD1;
            int kk = i - co * KD1;
            int k  = kk >> 8;
            int ci = kk & 255;
            wa_buf[i] = __float2half_rn(cw[(k * C_ + co) * C_ + ci]);
        }
    } else if (b < PREP_WT2_BLKS + PREP_WA_BLKS + PREP_AMH_BLKS) {
        int i = (b - PREP_WT2_BLKS - PREP_WA_BLKS) * 256 + tid;
        if (i < 80 * 32) {
            int r = i >> 5;
            int v = i & 31;
            float val = 0.f;
            if (r < 75 && v < V_) {
                int k = r / V_;
                int w = r - k * V_;
                int idx = (k * V_ + v) * V_ + w;
                val = A[idx] * Mm[idx];
            }
            amh_buf[i] = __float2half_rn(val);
        }
    } else {
        __shared__ float S[K_ * V_];
        if (tid < K_ * V_) {
            int k = tid / V_;
            int w = tid - k * V_;
            float s = 0.f;
            for (int v = 0; v < V_; ++v) {
                int idx = (k * V_ + v) * V_ + w;
                s += A[idx] * Mm[idx];
            }
            S[tid] = s;
        }
        __syncthreads();
        int c = tid;
        for (int w = 0; w < V_; ++w) {
            float s = 0.f;
            #pragma unroll
            for (int k = 0; k < K_; ++k)
                s += bias[k * C_ + c] * S[k * V_ + w];
            bcw_buf[c * V_ + w] = s;
        }
    }
}

// ---------------------------------------------------------------------------
// xa via MMA, 4 t's per block (proven round-8 version)
// ---------------------------------------------------------------------------
#define XAT 320
#define XB_BYTES (256 * 272)
#define XA_AOFF XB_BYTES
#define XA_SMEM3 (XB_BYTES + 80 * 80)   // 76032

__global__ void __launch_bounds__(XAT, 2) xa_mma_kernel(const float* __restrict__ x)
{
    extern __shared__ char sxm[];
    const uint32_t sb = smem_u32(sxm);
    const int tid  = threadIdx.x;
    const int lane = tid & 31;
    const int wid  = tid >> 5;
    const int s    = wid >> 1;
    const int h    = wid & 1;
    const int t0   = blockIdx.x * 4;
    const int n    = blockIdx.y;

    for (int i = tid; i < 256 * 28; i += XAT) {
        const int row = i / 28;
        const int r   = i - row * 28;
        const int tc  = r / 7;
        const int v   = 25 + (r - tc * 7);
        *(__half*)(sxm + row * 272 + (tc * 32 + v) * 2) = __half(0);
    }
    {
        uint4 v = ((const uint4*)amh_buf)[tid];
        *(uint4*)(sxm + XA_AOFF + (tid >> 2) * 80 + (tid & 3) * 16) = v;
    }
    const float* xb = x + ((size_t)(n * C_) * T_ + t0) * V_;
    for (int i = tid; i < 256 * 25; i += XAT) {
        const int row = i / 25;
        const int f4  = i - row * 25;
        const float4 v = *(const float4*)(xb + (size_t)row * (T_ * V_) + f4 * 4);
        const int e0 = f4 * 4;
        #pragma unroll
        for (int e = 0; e < 4; ++e) {
            const int tc = (e0 + e) / 25;
            const int vv = (e0 + e) - tc * 25;
            const float f = (e == 0) ? v.x : (e == 1) ? v.y : (e == 2) ? v.z : v.w;
            *(__half*)(sxm + row * 272 + (tc * 32 + vv) * 2) = __float2half_rn(f);
        }
    }
    __syncthreads();

    uint32_t aa[2][4];
    {
        const uint32_t abase = sb + XA_AOFF + (uint32_t)((s * 16 + (lane & 15)) * 80)
                               + (uint32_t)((lane >> 4) << 4);
        ldsm4(aa[0], abase);
        ldsm4(aa[1], abase + 32);
    }

    const uint32_t brow0 = sb + (uint32_t)((h * 128 + (lane & 7) + (((lane >> 4) & 1) << 3)) * 272)
                           + (uint32_t)(((lane >> 3) & 1) << 4);

    for (int tc = 0; tc < 4; ++tc) {
        float acc[16][4];
        #pragma unroll
        for (int nf = 0; nf < 16; ++nf)
            #pragma unroll
            for (int q = 0; q < 4; ++q) acc[nf][q] = 0.f;

        const uint32_t bt = brow0 + (uint32_t)(tc * 64);
        #pragma unroll
        for (int ks = 0; ks < 2; ++ks) {
            #pragma unroll
            for (int nb = 0; nb < 8; ++nb) {
                uint32_t bb[4];
                ldsm4(bb, bt + (uint32_t)(nb * 16 * 272) + (uint32_t)(ks * 32));
                mma16816(acc[nb * 2 + 0], aa[ks], bb[0], bb[1]);
                mma16816(acc[nb * 2 + 1], aa[ks], bb[2], bb[3]);
            }
        }

        __half* outb = xa_buf + ((size_t)n * J_ + (size_t)(t0 + tc) * V_) * KD1;
        #pragma unroll
        for (int hh = 0; hh < 2; ++hh) {
            const int row = s * 16 + (lane >> 2) + hh * 8;
            if (row < 75) {
                const int k = row / V_;
                const int w = row - k * V_;
                __half* orow = outb + (size_t)w * KD1 + k * C_ + h * 128 + (lane & 3) * 2;
                #pragma unroll
                for (int nf = 0; nf < 16; ++nf) {
                    __half2 p = __floats2half2_rn(acc[nf][hh * 2 + 0], acc[nf][hh * 2 + 1]);
                    *(__half2*)(orow + nf * 8) = p;
                }
            }
        }
    }
}

// ---------------------------------------------------------------------------
// GEMM geometry v4 (round-15 winner): CTA 128x128, 4 warps (2m x 2n),
// warp tile 64x64, k=64, 3-stage ring. Split A/B prefetch across ks=0/ks=1.
// ---------------------------------------------------------------------------
#define G_STAGE 32768
#define G_SMEM  98304
#define GT 128              // threads per CTA

// ---------------------------------------------------------------------------
// GEMM1: sgc = Wa @ xa -> bcw + BN1 + ReLU -> gt[n][j][c] fp16
// ---------------------------------------------------------------------------
#define IT1 12

__global__ void __launch_bounds__(GT, 2) gemm1_kernel(
    const float* __restrict__ g1, const float* __restrict__ b1,
    const float* __restrict__ m1, const float* __restrict__ v1)
{
    extern __shared__ char smraw[];
    const uint32_t sb = smem_u32(smraw);
    const int tid  = threadIdx.x;
    const int wid  = tid >> 5;         // 0..3
    const int lane = tid & 31;
    const int co0  = blockIdx.x * 128; // co fastest: L2 pairing of shared B
    const int j0   = blockIdx.y * 128;
    const int n    = blockIdx.z;
    const int cw = (wid & 1) * 64;     // 2 m-groups of 64 co
    const int jw = (wid >> 1) * 64;    // 2 n-groups of 64 j

    const __half* xan = xa_buf + (size_t)n * J_ * KD1;

    float acc[4][8][4];
    #pragma unroll
    for (int mi = 0; mi < 4; ++mi)
        #pragma unroll
        for (int nf = 0; nf < 8; ++nf)
            #pragma unroll
            for (int q = 0; q < 4; ++q) acc[mi][nf][q] = 0.f;

    auto load_A = [&](int it, int slot) {
        const uint32_t base = sb + (uint32_t)slot * G_STAGE;
        const int kb = it * 64;
        #pragma unroll
        for (int q = 0; q < 8; ++q) {
            const int c   = tid + q * GT;
            const int row = c >> 3;        // 0..127 co
            const int ch  = c & 7;
            const uint32_t sw = (uint32_t)((ch ^ (row & 7)) << 4);
            const __half* as = wa_buf + (size_t)(co0 + row) * KD1 + kb + ch * 8;
            cpa16(base + row * 128 + sw, as, 16);
        }
    };
    auto load_B = [&](int it, int slot) {
        const uint32_t base = sb + (uint32_t)slot * G_STAGE;
        const int kb = it * 64;
        #pragma unroll
        for (int q = 0; q < 8; ++q) {
            const int c   = tid + q * GT;
            const int row = c >> 3;        // 0..127 j
            const int ch  = c & 7;
            const uint32_t sw = (uint32_t)((ch ^ (row & 7)) << 4);
            const int jp = j0 + row;
            const bool v = jp < J_;
            const __half* bs = xan + (size_t)(v ? jp : 0) * KD1 + kb + ch * 8;
            cpa16(base + 16384 + row * 128 + sw, bs, v ? 16 : 0);
        }
    };

    load_A(0, 0); load_B(0, 0); cpa_commit();
    load_A(1, 1); load_B(1, 1); cpa_commit();

    const int rs  = lane & 7;
    const int hiA = lane >> 4;
    const int hiB = (lane >> 3) & 1;
    uint32_t rowA[4], rowB[4];
    #pragma unroll
    for (int mi = 0; mi < 4; ++mi)
        rowA[mi] = (uint32_t)((cw + mi * 16 + (lane & 15)) * 128);
    #pragma unroll
    for (int nb = 0; nb < 4; ++nb)
        rowB[nb] = (uint32_t)((jw + nb * 16 + (lane & 7) + (((lane >> 4) & 1) << 3)) * 128 + 16384);

    int wslot = 2, cslot = 0;
    for (int it = 0; it < IT1; ++it) {
        if (it < IT1 - 1) cpa_wait<1>(); else cpa_wait<0>();
        __syncthreads();
        const uint32_t base = sb + (uint32_t)cslot * G_STAGE;
        cslot = (cslot == 2) ? 0 : cslot + 1;

        #pragma unroll
        for (int ks = 0; ks < 4; ++ks) {
            uint32_t aa[4][4], bb[4][4];
            #pragma unroll
            for (int mi = 0; mi < 4; ++mi)
                ldsm4(aa[mi], base + rowA[mi] + (uint32_t)((((ks * 2 + hiA) ^ rs)) << 4));
            #pragma unroll
            for (int nb = 0; nb < 4; ++nb)
                ldsm4(bb[nb], base + rowB[nb] + (uint32_t)((((ks * 2 + hiB) ^ rs)) << 4));
            #pragma unroll
            for (int mi = 0; mi < 4; ++mi)
                #pragma unroll
                for (int nf = 0; nf < 8; ++nf) {
                    const int nb = nf >> 1;
                    if (nf & 1) mma16816(acc[mi][nf], aa[mi], bb[nb][2], bb[nb][3]);
                    else        mma16816(acc[mi][nf], aa[mi], bb[nb][0], bb[nb][1]);
                }
            if (it + 2 < IT1) {
                if (ks == 0) load_A(it + 2, wslot);
                else if (ks == 1) {
                    load_B(it + 2, wslot);
                    cpa_commit();
                    wslot = (wslot == 2) ? 0 : wslot + 1;
                }
            }
        }
    }
    __syncthreads();

    // epilogue: bcw + BN1 + ReLU -> smem transpose ts[128 j][136] -> gt
    __half* ts = (__half*)smraw;
    #pragma unroll
    for (int mi = 0; mi < 4; ++mi) {
        #pragma unroll
        for (int hh = 0; hh < 2; ++hh) {
            const int col = cw + mi * 16 + (lane >> 2) + hh * 8;   // 0..127
            const int cog = co0 + col;
            const float scl = g1[cog] * rsqrtf(v1[cog] + BN_EPS);
            const float shf = b1[cog] - m1[cog] * scl;
            const float* bcr = bcw_buf + cog * V_;
            #pragma unroll
            for (int nf = 0; nf < 8; ++nf) {
                const int jl = jw + nf * 8 + (lane & 3) * 2;
                const int jg = j0 + jl;
                const int w0 = jg % 25;
                const int w1 = (w0 == 24) ? 0 : w0 + 1;
                float r0 = acc[mi][nf][hh * 2 + 0] + bcr[w0];
                float r1 = acc[mi][nf][hh * 2 + 1] + bcr[w1];
                r0 = fmaf(r0, scl, shf);
                r1 = fmaf(r1, scl, shf);
                r0 = r0 > 0.f ? r0 : 0.f;
                r1 = r1 > 0.f ? r1 : 0.f;
                ts[jl * 136 + col]       = __float2half_rn(r0);
                ts[(jl + 1) * 136 + col] = __float2half_rn(r1);
            }
        }
    }
    __syncthreads();

    __half* gout = gt_buf + (size_t)n * J_ * C_;
    #pragma unroll
    for (int p = 0; p < 16; ++p) {
        const int idx = p * GT + tid;    // 2048 uint4
        const int cc = idx & 15;
        const int j  = idx >> 4;
        const int jg = j0 + j;
        if (jg < J_) {
            uint4 vv = *(const uint4*)(ts + j * 136 + cc * 8);
            *(uint4*)(gout + (size_t)jg * C_ + co0 + cc * 8) = vv;
        }
    }
}

// ---------------------------------------------------------------------------
// GEMM2: temporal conv (K = 9*256) + BN2 + ReLU + residual
// ---------------------------------------------------------------------------
#define IT2 36

__global__ void __launch_bounds__(GT, 2) gemm2_kernel(
    const float* __restrict__ x, const float* __restrict__ tcb,
    const float* __restrict__ g2, const float* __restrict__ b2,
    const float* __restrict__ m2, const float* __restrict__ v2,
    float* __restrict__ out)
{
    extern __shared__ char smraw2[];
    const uint32_t sb = smem_u32(smraw2);
    const int tid  = threadIdx.x;
    const int wid  = tid >> 5;
    const int lane = tid & 31;
    const int co0  = blockIdx.x * 128; // co fastest: pair shares B tile via L2
    const int j0   = blockIdx.y * 128;
    const int n    = blockIdx.z;
    const int cw = (wid & 1) * 64;
    const int jw = (wid >> 1) * 64;

    const __half* gtn = gt_buf + (size_t)n * J_ * C_;

    float acc[4][8][4];
    #pragma unroll
    for (int mi = 0; mi < 4; ++mi)
        #pragma unroll
        for (int nf = 0; nf < 8; ++nf)
            #pragma unroll
            for (int q = 0; q < 4; ++q) acc[mi][nf][q] = 0.f;

    auto load_A = [&](int it, int slot) {
        const uint32_t base = sb + (uint32_t)slot * G_STAGE;
        const int dt  = it >> 2;
        const int cic = (it & 3) << 6;
        #pragma unroll
        for (int q = 0; q < 8; ++q) {
            const int c   = tid + q * GT;
            const int row = c >> 3;
            const int ch  = c & 7;
            const uint32_t sw = (uint32_t)((ch ^ (row & 7)) << 4);
            const __half* as = wt2_buf + (size_t)dt * (C_ * C_) +
                               (size_t)(co0 + row) * C_ + cic + ch * 8;
            cpa16(base + row * 128 + sw, as, 16);
        }
    };
    auto load_B = [&](int it, int slot) {
        const uint32_t base = sb + (uint32_t)slot * G_STAGE;
        const int dt  = it >> 2;
        const int cic = (it & 3) << 6;
        const int s   = (dt - (TK_ - 1) / 2) * V_;
        #pragma unroll
        for (int q = 0; q < 8; ++q) {
            const int c   = tid + q * GT;
            const int row = c >> 3;
            const int ch  = c & 7;
            const uint32_t sw = (uint32_t)((ch ^ (row & 7)) << 4);
            const int jp = j0 + row + s;
            const bool v = (jp >= 0) && (jp < J_);
            const __half* bs = gtn + (size_t)(v ? jp : 0) * C_ + cic + ch * 8;
            cpa16(base + 16384 + row * 128 + sw, bs, v ? 16 : 0);
        }
    };

    load_A(0, 0); load_B(0, 0); cpa_commit();
    load_A(1, 1); load_B(1, 1); cpa_commit();

    const int rs  = lane & 7;
    const int hiA = lane >> 4;
    const int hiB = (lane >> 3) & 1;
    uint32_t rowA[4], rowB[4];
    #pragma unroll
    for (int mi = 0; mi < 4; ++mi)
        rowA[mi] = (uint32_t)((cw + mi * 16 + (lane & 15)) * 128);
    #pragma unroll
    for (int nb = 0; nb < 4; ++nb)
        rowB[nb] = (uint32_t)((jw + nb * 16 + (lane & 7) + (((lane >> 4) & 1) << 3)) * 128 + 16384);

    int wslot = 2, cslot = 0;
    for (int it = 0; it < IT2; ++it) {
        if (it < IT2 - 1) cpa_wait<1>(); else cpa_wait<0>();
        __syncthreads();
        const uint32_t base = sb + (uint32_t)cslot * G_STAGE;
        cslot = (cslot == 2) ? 0 : cslot + 1;

        #pragma unroll
        for (int ks = 0; ks < 4; ++ks) {
            uint32_t aa[4][4], bb[4][4];
            #pragma unroll
            for (int mi = 0; mi < 4; ++mi)
                ldsm4(aa[mi], base + rowA[mi] + (uint32_t)((((ks * 2 + hiA) ^ rs)) << 4));
            #pragma unroll
            for (int nb = 0; nb < 4; ++nb)
                ldsm4(bb[nb], base + rowB[nb] + (uint32_t)((((ks * 2 + hiB) ^ rs)) << 4));
            #pragma unroll
            for (int mi = 0; mi < 4; ++mi)
                #pragma unroll
                for (int nf = 0; nf < 8; ++nf) {
                    const int nb = nf >> 1;
                    if (nf & 1) mma16816(acc[mi][nf], aa[mi], bb[nb][2], bb[nb][3]);
                    else        mma16816(acc[mi][nf], aa[mi], bb[nb][0], bb[nb][1]);
                }
            if (it + 2 < IT2) {
                if (ks == 0) load_A(it + 2, wslot);
                else if (ks == 1) {
                    load_B(it + 2, wslot);
                    cpa_commit();
                    wslot = (wslot == 2) ? 0 : wslot + 1;
                }
            }
        }
    }

    // epilogue: BN2 + ReLU + residual
    #pragma unroll
    for (int mi = 0; mi < 4; ++mi) {
        #pragma unroll
        for (int hh = 0; hh < 2; ++hh) {
            const int co = co0 + cw + mi * 16 + (lane >> 2) + hh * 8;
            const float scl = g2[co] * rsqrtf(v2[co] + BN_EPS);
            const float shf = b2[co] - m2[co] * scl + tcb[co] * scl;
            const float* xr = x   + (size_t)(n * C_ + co) * J_;
            float* orow     = out + (size_t)(n * C_ + co) * J_;
            #pragma unroll
            for (int nf = 0; nf < 8; ++nf) {
                const int jj = j0 + jw + nf * 8 + (lane & 3) * 2;
                if (jj < J_) {
                    float v0 = fmaf(acc[mi][nf][hh * 2 + 0], scl, shf);
                    float v1 = fmaf(acc[mi][nf][hh * 2 + 1], scl, shf);
                    v0 = v0 > 0.f ? v0 : 0.f;
                    v1 = v1 > 0.f ? v1 : 0.f;
                    float2 xv = *(const float2*)(xr + jj);
                    float2 o;
                    o.x = v0 + xv.x;
                    o.y = v1 + xv.y;
                    *(float2*)(orow + jj) = o;
                }
            }
        }
    }
}

// ---------------------------------------------------------------------------
extern "C" void kernel_launch(void* const* d_in, const int* in_sizes, int n_in,
                              void* d_out, int out_size)
{
    const float* x   = (const float*)d_in[0];
    const float* A   = (const float*)d_in[1];
    // d_in[2] = att_A (unused)
    const float* Mm  = (const float*)d_in[3];
    const float* W   = (const float*)d_in[4];
    const float* cb  = (const float*)d_in[5];
    const float* g1  = (const float*)d_in[6];
    const float* b1  = (const float*)d_in[7];
    const float* m1  = (const float*)d_in[8];
    const float* v1  = (const float*)d_in[9];
    const float* tw  = (const float*)d_in[10];
    const float* tcb = (const float*)d_in[11];
    const float* g2  = (const float*)d_in[12];
    const float* b2  = (const float*)d_in[13];
    const float* m2  = (const float*)d_in[14];
    const float* v2  = (const float*)d_in[15];
    float* out = (float*)d_out;

    cudaFuncSetAttribute(xa_mma_kernel, cudaFuncAttributeMaxDynamicSharedMemorySize, XA_SMEM3);
    cudaFuncSetAttribute(gemm1_kernel,  cudaFuncAttributeMaxDynamicSharedMemorySize, G_SMEM);
    cudaFuncSetAttribute(gemm2_kernel,  cudaFuncAttributeMaxDynamicSharedMemorySize, G_SMEM);

    // merged prep (wt2 | wa | amh | bcw)
    prep_kernel<<<PREP_BLKS, 256>>>(tw, W, A, Mm, cb);

    // xa via MMA, 4 t's per block
    dim3 gxa(T_ / 4, N_);
    xa_mma_kernel<<<gxa, XAT, XA_SMEM3>>>(x);

    // GEMM1: S_GC + BN1 + ReLU -> gt  (co fastest in grid.x)
    dim3 gg1(C_ / 128, (J_ + 127) / 128, N_);
    gemm1_kernel<<<gg1, GT, G_SMEM>>>(g1, b1, m1, v1);

    // GEMM2: temporal conv + BN2 + ReLU + residual (co fastest in grid.x)
    dim3 gg2(C_ / 128, (J_ + 127) / 128, N_);
    gemm2_kernel<<<gg2, GT, G_SMEM>>>(x, tcb, g2, b2, m2, v2, out);
}

// round 17
// speedup vs baseline: 1.0897x; 1.0897x over previous
#include <cuda_runtime.h>
#include <cuda_fp16.h>
#include <cstdint>

#define N_ 16
#define C_ 256
#define T_ 300
#define V_ 25
#define K_ 3
#define TK_ 9
#define J_ 7500
#define KD1 768            // GEMM1 K-dim (k,ci)
#define BN_EPS 1e-5f

// static device scratch
__device__ __align__(256) __half xa_buf[(size_t)N_ * J_ * KD1];   // 184 MB
__device__ __align__(256) __half gt_buf[(size_t)N_ * J_ * C_];    // 61.4 MB
__device__ __align__(256) __half wt2_buf[TK_ * C_ * C_];          // [dt][co][ci]
__device__ __align__(256) __half wa_buf[C_ * KD1];                // [co][(k,ci)]
__device__ __align__(256) __half amh_buf[80 * 32];                // [kw-row][v] fp16
__device__ float bcw_buf[C_ * V_];                                // bias*sum(AM)

// ---------------------------------------------------------------------------
// PTX helpers
// ---------------------------------------------------------------------------
__device__ __forceinline__ uint32_t smem_u32(const void* p) {
    uint32_t a;
    asm("{ .reg .u64 t; cvta.to.shared.u64 t, %1; cvt.u32.u64 %0, t; }" : "=r"(a) : "l"(p));
    return a;
}
__device__ __forceinline__ void ldsm4(uint32_t* r, uint32_t addr) {
    asm volatile("ldmatrix.sync.aligned.m8n8.x4.shared.b16 {%0,%1,%2,%3}, [%4];"
                 : "=r"(r[0]), "=r"(r[1]), "=r"(r[2]), "=r"(r[3]) : "r"(addr));
}
__device__ __forceinline__ void mma16816(float* c, const uint32_t* a,
                                         uint32_t b0, uint32_t b1) {
    asm("mma.sync.aligned.m16n8k16.row.col.f32.f16.f16.f32 "
        "{%0,%1,%2,%3}, {%4,%5,%6,%7}, {%8,%9}, {%0,%1,%2,%3};"
        : "+f"(c[0]), "+f"(c[1]), "+f"(c[2]), "+f"(c[3])
        : "r"(a[0]), "r"(a[1]), "r"(a[2]), "r"(a[3]), "r"(b0), "r"(b1));
}
__device__ __forceinline__ void cpa16(uint32_t dst, const void* src, int srcsize) {
    asm volatile("cp.async.cg.shared.global [%0], [%1], 16, %2;"
                 :: "r"(dst), "l"(src), "r"(srcsize));
}
__device__ __forceinline__ void cpa_commit() {
    asm volatile("cp.async.commit_group;" ::: "memory");
}
template <int NN>
__device__ __forceinline__ void cpa_wait() {
    asm volatile("cp.async.wait_group %0;" :: "n"(NN) : "memory");
}

// ---------------------------------------------------------------------------
// merged prep kernel: wt2 | wa | amh | bcw by blockIdx range  (proven)
// ---------------------------------------------------------------------------
#define PREP_WT2_BLKS 2304
#define PREP_WA_BLKS  768
#define PREP_AMH_BLKS 10
#define PREP_BLKS (PREP_WT2_BLKS + PREP_WA_BLKS + PREP_AMH_BLKS + 1)

__global__ void prep_kernel(const float* __restrict__ tw, const float* __restrict__ cw,
                            const float* __restrict__ A, const float* __restrict__ Mm,
                            const float* __restrict__ bias) {
    const int b = blockIdx.x;
    const int tid = threadIdx.x;
    if (b < PREP_WT2_BLKS) {
        int i = b * 256 + tid;
        if (i < TK_ * C_ * C_) {
            int dt = i / (C_ * C_);
            int r  = i - dt * C_ * C_;
            int co = r >> 8;
            int ci = r & 255;
            wt2_buf[i] = __float2half_rn(tw[(co * C_ + ci) * TK_ + dt]);
        }
    } else if (b < PREP_WT2_BLKS + PREP_WA_BLKS) {
        int i = (b - PREP_WT2_BLKS) * 256 + tid;
        if (i < C_ * KD1) {
            int co = i / KD1;
            int kk = i - co * KD1;
            int k  = kk >> 8;
            int ci = kk & 255;
            wa_buf[i] = __float2half_rn(cw[(k * C_ + co) * C_ + ci]);
        }
    } else if (b < PREP_WT2_BLKS + PREP_WA_BLKS + PREP_AMH_BLKS) {
        int i = (b - PREP_WT2_BLKS - PREP_WA_BLKS) * 256 + tid;
        if (i < 80 * 32) {
            int r = i >> 5;
            int v = i & 31;
            float val = 0.f;
            if (r < 75 && v < V_) {
                int k = r / V_;
                int w = r - k * V_;
                int idx = (k * V_ + v) * V_ + w;
                val = A[idx] * Mm[idx];
            }
            amh_buf[i] = __float2half_rn(val);
        }
    } else {
        __shared__ float S[K_ * V_];
        if (tid < K_ * V_) {
            int k = tid / V_;
            int w = tid - k * V_;
            float s = 0.f;
            for (int v = 0; v < V_; ++v) {
                int idx = (k * V_ + v) * V_ + w;
                s += A[idx] * Mm[idx];
            }
            S[tid] = s;
        }
        __syncthreads();
        int c = tid;
        for (int w = 0; w < V_; ++w) {
            float s = 0.f;
            #pragma unroll
            for (int k = 0; k < K_; ++k)
                s += bias[k * C_ + c] * S[k * V_ + w];
            bcw_buf[c * V_ + w] = s;
        }
    }
}

// ---------------------------------------------------------------------------
// xa via MMA, 4 t's per block (proven round-8 version)
// ---------------------------------------------------------------------------
#define XAT 320
#define XB_BYTES (256 * 272)
#define XA_AOFF XB_BYTES
#define XA_SMEM3 (XB_BYTES + 80 * 80)   // 76032

__global__ void __launch_bounds__(XAT, 2) xa_mma_kernel(const float* __restrict__ x)
{
    extern __shared__ char sxm[];
    const uint32_t sb = smem_u32(sxm);
    const int tid  = threadIdx.x;
    const int lane = tid & 31;
    const int wid  = tid >> 5;
    const int s    = wid >> 1;
    const int h    = wid & 1;
    const int t0   = blockIdx.x * 4;
    const int n    = blockIdx.y;

    for (int i = tid; i < 256 * 28; i += XAT) {
        const int row = i / 28;
        const int r   = i - row * 28;
        const int tc  = r / 7;
        const int v   = 25 + (r - tc * 7);
        *(__half*)(sxm + row * 272 + (tc * 32 + v) * 2) = __half(0);
    }
    {
        uint4 v = ((const uint4*)amh_buf)[tid];
        *(uint4*)(sxm + XA_AOFF + (tid >> 2) * 80 + (tid & 3) * 16) = v;
    }
    const float* xb = x + ((size_t)(n * C_) * T_ + t0) * V_;
    for (int i = tid; i < 256 * 25; i += XAT) {
        const int row = i / 25;
        const int f4  = i - row * 25;
        const float4 v = *(const float4*)(xb + (size_t)row * (T_ * V_) + f4 * 4);
        const int e0 = f4 * 4;
        #pragma unroll
        for (int e = 0; e < 4; ++e) {
            const int tc = (e0 + e) / 25;
            const int vv = (e0 + e) - tc * 25;
            const float f = (e == 0) ? v.x : (e == 1) ? v.y : (e == 2) ? v.z : v.w;
            *(__half*)(sxm + row * 272 + (tc * 32 + vv) * 2) = __float2half_rn(f);
        }
    }
    __syncthreads();

    uint32_t aa[2][4];
    {
        const uint32_t abase = sb + XA_AOFF + (uint32_t)((s * 16 + (lane & 15)) * 80)
                               + (uint32_t)((lane >> 4) << 4);
        ldsm4(aa[0], abase);
        ldsm4(aa[1], abase + 32);
    }

    const uint32_t brow0 = sb + (uint32_t)((h * 128 + (lane & 7) + (((lane >> 4) & 1) << 3)) * 272)
                           + (uint32_t)(((lane >> 3) & 1) << 4);

    for (int tc = 0; tc < 4; ++tc) {
        float acc[16][4];
        #pragma unroll
        for (int nf = 0; nf < 16; ++nf)
            #pragma unroll
            for (int q = 0; q < 4; ++q) acc[nf][q] = 0.f;

        const uint32_t bt = brow0 + (uint32_t)(tc * 64);
        #pragma unroll
        for (int ks = 0; ks < 2; ++ks) {
            #pragma unroll
            for (int nb = 0; nb < 8; ++nb) {
                uint32_t bb[4];
                ldsm4(bb, bt + (uint32_t)(nb * 16 * 272) + (uint32_t)(ks * 32));
                mma16816(acc[nb * 2 + 0], aa[ks], bb[0], bb[1]);
                mma16816(acc[nb * 2 + 1], aa[ks], bb[2], bb[3]);
            }
        }

        __half* outb = xa_buf + ((size_t)n * J_ + (size_t)(t0 + tc) * V_) * KD1;
        #pragma unroll
        for (int hh = 0; hh < 2; ++hh) {
            const int row = s * 16 + (lane >> 2) + hh * 8;
            if (row < 75) {
                const int k = row / V_;
                const int w = row - k * V_;
                __half* orow = outb + (size_t)w * KD1 + k * C_ + h * 128 + (lane & 3) * 2;
                #pragma unroll
                for (int nf = 0; nf < 16; ++nf) {
                    __half2 p = __floats2half2_rn(acc[nf][hh * 2 + 0], acc[nf][hh * 2 + 1]);
                    *(__half2*)(orow + nf * 8) = p;
                }
            }
        }
    }
}

// ---------------------------------------------------------------------------
// GEMM geometry v4 (round-15 winner): CTA 128(co) x 128(j), FOUR warps
// (128 thr) as 2m x 2n, warp tile 64x64 (acc 128 regs). k=64, 3-stage ring,
// staggered full prefetch at ks==0, j-fastest grid.
// ---------------------------------------------------------------------------
#define G_STAGE 32768
#define G_SMEM  98304
#define GT 128              // threads per CTA

// ---------------------------------------------------------------------------
// GEMM1: sgc = Wa @ xa -> bcw + BN1 + ReLU -> gt[n][j][c] fp16
// ---------------------------------------------------------------------------
#define IT1 12

__global__ void __launch_bounds__(GT, 2) gemm1_kernel(
    const float* __restrict__ g1, const float* __restrict__ b1,
    const float* __restrict__ m1, const float* __restrict__ v1)
{
    extern __shared__ char smraw[];
    const uint32_t sb = smem_u32(smraw);
    const int tid  = threadIdx.x;
    const int wid  = tid >> 5;         // 0..3
    const int lane = tid & 31;
    const int j0   = blockIdx.x * 128;
    const int co0  = blockIdx.y * 128;
    const int n    = blockIdx.z;
    const int cw = (wid & 1) * 64;     // 2 m-groups of 64 co
    const int jw = (wid >> 1) * 64;    // 2 n-groups of 64 j

    const __half* xan = xa_buf + (size_t)n * J_ * KD1;

    float acc[4][8][4];
    #pragma unroll
    for (int mi = 0; mi < 4; ++mi)
        #pragma unroll
        for (int nf = 0; nf < 8; ++nf)
            #pragma unroll
            for (int q = 0; q < 4; ++q) acc[mi][nf][q] = 0.f;

    auto load_stage = [&](int it, int slot) {
        const uint32_t base = sb + (uint32_t)slot * G_STAGE;
        const int kb = it * 64;
        #pragma unroll
        for (int q = 0; q < 8; ++q) {
            const int c   = tid + q * GT;
            const int row = c >> 3;        // 0..127 co
            const int ch  = c & 7;
            const uint32_t sw = (uint32_t)((ch ^ (row & 7)) << 4);
            const __half* as = wa_buf + (size_t)(co0 + row) * KD1 + kb + ch * 8;
            cpa16(base + row * 128 + sw, as, 16);
        }
        #pragma unroll
        for (int q = 0; q < 8; ++q) {
            const int c   = tid + q * GT;
            const int row = c >> 3;        // 0..127 j
            const int ch  = c & 7;
            const uint32_t sw = (uint32_t)((ch ^ (row & 7)) << 4);
            const int jp = j0 + row;
            const bool v = jp < J_;
            const __half* bs = xan + (size_t)(v ? jp : 0) * KD1 + kb + ch * 8;
            cpa16(base + 16384 + row * 128 + sw, bs, v ? 16 : 0);
        }
        cpa_commit();
    };

    load_stage(0, 0);
    load_stage(1, 1);

    const int rs  = lane & 7;
    const int hiA = lane >> 4;
    const int hiB = (lane >> 3) & 1;
    uint32_t rowA[4], rowB[4];
    #pragma unroll
    for (int mi = 0; mi < 4; ++mi)
        rowA[mi] = (uint32_t)((cw + mi * 16 + (lane & 15)) * 128);
    #pragma unroll
    for (int nb = 0; nb < 4; ++nb)
        rowB[nb] = (uint32_t)((jw + nb * 16 + (lane & 7) + (((lane >> 4) & 1) << 3)) * 128 + 16384);

    int wslot = 2, cslot = 0;
    for (int it = 0; it < IT1; ++it) {
        if (it < IT1 - 1) cpa_wait<1>(); else cpa_wait<0>();
        __syncthreads();
        const uint32_t base = sb + (uint32_t)cslot * G_STAGE;
        cslot = (cslot == 2) ? 0 : cslot + 1;

        #pragma unroll
        for (int ks = 0; ks < 4; ++ks) {
            uint32_t aa[4][4], bb[4][4];
            #pragma unroll
            for (int mi = 0; mi < 4; ++mi)
                ldsm4(aa[mi], base + rowA[mi] + (uint32_t)((((ks * 2 + hiA) ^ rs)) << 4));
            #pragma unroll
            for (int nb = 0; nb < 4; ++nb)
                ldsm4(bb[nb], base + rowB[nb] + (uint32_t)((((ks * 2 + hiB) ^ rs)) << 4));
            #pragma unroll
            for (int mi = 0; mi < 4; ++mi)
                #pragma unroll
                for (int nf = 0; nf < 8; ++nf) {
                    const int nb = nf >> 1;
                    if (nf & 1) mma16816(acc[mi][nf], aa[mi], bb[nb][2], bb[nb][3]);
                    else        mma16816(acc[mi][nf], aa[mi], bb[nb][0], bb[nb][1]);
                }
            if (ks == 0 && it + 2 < IT1) {
                load_stage(it + 2, wslot);
                wslot = (wslot == 2) ? 0 : wslot + 1;
            }
        }
    }
    __syncthreads();

    // epilogue: bcw + BN1 + ReLU -> smem transpose ts[128 j][136] -> gt
    __half* ts = (__half*)smraw;
    #pragma unroll
    for (int mi = 0; mi < 4; ++mi) {
        #pragma unroll
        for (int hh = 0; hh < 2; ++hh) {
            const int col = cw + mi * 16 + (lane >> 2) + hh * 8;   // 0..127
            const int cog = co0 + col;
            const float scl = g1[cog] * rsqrtf(v1[cog] + BN_EPS);
            const float shf = b1[cog] - m1[cog] * scl;
            const float* bcr = bcw_buf + cog * V_;
            #pragma unroll
            for (int nf = 0; nf < 8; ++nf) {
                const int jl = jw + nf * 8 + (lane & 3) * 2;
                const int jg = j0 + jl;
                const int w0 = jg % 25;
                const int w1 = (w0 == 24) ? 0 : w0 + 1;
                float r0 = acc[mi][nf][hh * 2 + 0] + bcr[w0];
                float r1 = acc[mi][nf][hh * 2 + 1] + bcr[w1];
                r0 = fmaf(r0, scl, shf);
                r1 = fmaf(r1, scl, shf);
                r0 = r0 > 0.f ? r0 : 0.f;
                r1 = r1 > 0.f ? r1 : 0.f;
                ts[jl * 136 + col]       = __float2half_rn(r0);
                ts[(jl + 1) * 136 + col] = __float2half_rn(r1);
            }
        }
    }
    __syncthreads();

    __half* gout = gt_buf + (size_t)n * J_ * C_;
    #pragma unroll
    for (int p = 0; p < 16; ++p) {
        const int idx = p * GT + tid;    // 2048 uint4
        const int cc = idx & 15;
        const int j  = idx >> 4;
        const int jg = j0 + j;
        if (jg < J_) {
            uint4 vv = *(const uint4*)(ts + j * 136 + cc * 8);
            *(uint4*)(gout + (size_t)jg * C_ + co0 + cc * 8) = vv;
        }
    }
}

// ---------------------------------------------------------------------------
// GEMM2: temporal conv (K = 9*256) + BN2 + ReLU + residual
// ---------------------------------------------------------------------------
#define IT2 36

__global__ void __launch_bounds__(GT, 2) gemm2_kernel(
    const float* __restrict__ x, const float* __restrict__ tcb,
    const float* __restrict__ g2, const float* __restrict__ b2,
    const float* __restrict__ m2, const float* __restrict__ v2,
    float* __restrict__ out)
{
    extern __shared__ char smraw2[];
    const uint32_t sb = smem_u32(smraw2);
    const int tid  = threadIdx.x;
    const int wid  = tid >> 5;
    const int lane = tid & 31;
    const int j0   = blockIdx.x * 128;
    const int co0  = blockIdx.y * 128;
    const int n    = blockIdx.z;
    const int cw = (wid & 1) * 64;
    const int jw = (wid >> 1) * 64;

    const __half* gtn = gt_buf + (size_t)n * J_ * C_;

    float acc[4][8][4];
    #pragma unroll
    for (int mi = 0; mi < 4; ++mi)
        #pragma unroll
        for (int nf = 0; nf < 8; ++nf)
            #pragma unroll
            for (int q = 0; q < 4; ++q) acc[mi][nf][q] = 0.f;

    auto load_stage = [&](int it, int slot) {
        const uint32_t base = sb + (uint32_t)slot * G_STAGE;
        const int dt  = it >> 2;
        const int cic = (it & 3) << 6;
        const int s   = (dt - (TK_ - 1) / 2) * V_;
        #pragma unroll
        for (int q = 0; q < 8; ++q) {
            const int c   = tid + q * GT;
            const int row = c >> 3;
            const int ch  = c & 7;
            const uint32_t sw = (uint32_t)((ch ^ (row & 7)) << 4);
            const __half* as = wt2_buf + (size_t)dt * (C_ * C_) +
                               (size_t)(co0 + row) * C_ + cic + ch * 8;
            cpa16(base + row * 128 + sw, as, 16);
        }
        #pragma unroll
        for (int q = 0; q < 8; ++q) {
            const int c   = tid + q * GT;
            const int row = c >> 3;
            const int ch  = c & 7;
            const uint32_t sw = (uint32_t)((ch ^ (row & 7)) << 4);
            const int jp = j0 + row + s;
            const bool v = (jp >= 0) && (jp < J_);
            const __half* bs = gtn + (size_t)(v ? jp : 0) * C_ + cic + ch * 8;
            cpa16(base + 16384 + row * 128 + sw, bs, v ? 16 : 0);
        }
        cpa_commit();
    };

    load_stage(0, 0);
    load_stage(1, 1);

    const int rs  = lane & 7;
    const int hiA = lane >> 4;
    const int hiB = (lane >> 3) & 1;
    uint32_t rowA[4], rowB[4];
    #pragma unroll
    for (int mi = 0; mi < 4; ++mi)
        rowA[mi] = (uint32_t)((cw + mi * 16 + (lane & 15)) * 128);
    #pragma unroll
    for (int nb = 0; nb < 4; ++nb)
        rowB[nb] = (uint32_t)((jw + nb * 16 + (lane & 7) + (((lane >> 4) & 1) << 3)) * 128 + 16384);

    int wslot = 2, cslot = 0;
    for (int it = 0; it < IT2; ++it) {
        if (it < IT2 - 1) cpa_wait<1>(); else cpa_wait<0>();
        __syncthreads();
        const uint32_t base = sb + (uint32_t)cslot * G_STAGE;
        cslot = (cslot == 2) ? 0 : cslot + 1;

        #pragma unroll
        for (int ks = 0; ks < 4; ++ks) {
            uint32_t aa[4][4], bb[4][4];
            #pragma unroll
            for (int mi = 0; mi < 4; ++mi)
                ldsm4(aa[mi], base + rowA[mi] + (uint32_t)((((ks * 2 + hiA) ^ rs)) << 4));
            #pragma unroll
            for (int nb = 0; nb < 4; ++nb)
                ldsm4(bb[nb], base + rowB[nb] + (uint32_t)((((ks * 2 + hiB) ^ rs)) << 4));
            #pragma unroll
            for (int mi = 0; mi < 4; ++mi)
                #pragma unroll
                for (int nf = 0; nf < 8; ++nf) {
                    const int nb = nf >> 1;
                    if (nf & 1) mma16816(acc[mi][nf], aa[mi], bb[nb][2], bb[nb][3]);
                    else        mma16816(acc[mi][nf], aa[mi], bb[nb][0], bb[nb][1]);
                }
            if (ks == 0 && it + 2 < IT2) {
                load_stage(it + 2, wslot);
                wslot = (wslot == 2) ? 0 : wslot + 1;
            }
        }
    }

    // epilogue: BN2 + ReLU + residual
    #pragma unroll
    for (int mi = 0; mi < 4; ++mi) {
        #pragma unroll
        for (int hh = 0; hh < 2; ++hh) {
            const int co = co0 + cw + mi * 16 + (lane >> 2) + hh * 8;
            const float scl = g2[co] * rsqrtf(v2[co] + BN_EPS);
            const float shf = b2[co] - m2[co] * scl + tcb[co] * scl;
            const float* xr = x   + (size_t)(n * C_ + co) * J_;
            float* orow     = out + (size_t)(n * C_ + co) * J_;
            #pragma unroll
            for (int nf = 0; nf < 8; ++nf) {
                const int jj = j0 + jw + nf * 8 + (lane & 3) * 2;
                if (jj < J_) {
                    float v0 = fmaf(acc[mi][nf][hh * 2 + 0], scl, shf);
                    float v1 = fmaf(acc[mi][nf][hh * 2 + 1], scl, shf);
                    v0 = v0 > 0.f ? v0 : 0.f;
                    v1 = v1 > 0.f ? v1 : 0.f;
                    float2 xv = *(const float2*)(xr + jj);
                    float2 o;
                    o.x = v0 + xv.x;
                    o.y = v1 + xv.y;
                    *(float2*)(orow + jj) = o;
                }
            }
        }
    }
}

// ---------------------------------------------------------------------------
extern "C" void kernel_launch(void* const* d_in, const int* in_sizes, int n_in,
                              void* d_out, int out_size)
{
    const float* x   = (const float*)d_in[0];
    const float* A   = (const float*)d_in[1];
    // d_in[2] = att_A (unused)
    const float* Mm  = (const float*)d_in[3];
    const float* W   = (const float*)d_in[4];
    const float* cb  = (const float*)d_in[5];
    const float* g1  = (const float*)d_in[6];
    const float* b1  = (const float*)d_in[7];
    const float* m1  = (const float*)d_in[8];
    const float* v1  = (const float*)d_in[9];
    const float* tw  = (const float*)d_in[10];
    const float* tcb = (const float*)d_in[11];
    const float* g2  = (const float*)d_in[12];
    const float* b2  = (const float*)d_in[13];
    const float* m2  = (const float*)d_in[14];
    const float* v2  = (const float*)d_in[15];
    float* out = (float*)d_out;

    cudaFuncSetAttribute(xa_mma_kernel, cudaFuncAttributeMaxDynamicSharedMemorySize, XA_SMEM3);
    cudaFuncSetAttribute(gemm1_kernel,  cudaFuncAttributeMaxDynamicSharedMemorySize, G_SMEM);
    cudaFuncSetAttribute(gemm2_kernel,  cudaFuncAttributeMaxDynamicSharedMemorySize, G_SMEM);

    // merged prep (wt2 | wa | amh | bcw)
    prep_kernel<<<PREP_BLKS, 256>>>(tw, W, A, Mm, cb);

    // xa via MMA, 4 t's per block
    dim3 gxa(T_ / 4, N_);
    xa_mma_kernel<<<gxa, XAT, XA_SMEM3>>>(x);

    // GEMM1: S_GC + BN1 + ReLU -> gt  (j fastest in grid.x)
    dim3 gg1((J_ + 127) / 128, C_ / 128, N_);
    gemm1_kernel<<<gg1, GT, G_SMEM>>>(g1, b1, m1, v1);

    // GEMM2: temporal conv + BN2 + ReLU + residual (j fastest in grid.x)
    dim3 gg2((J_ + 127) / 128, C_ / 128, N_);
    gemm2_kernel<<<gg2, GT, G_SMEM>>>(x, tcb, g2, b2, m2, v2, out);
}